// round 6
// baseline (speedup 1.0000x reference)
#include <cuda_runtime.h>

#define BB  16
#define LL  128
#define LRR 128
#define VV  32000
#define NONE 0x7fffffff

// Scratch (no allocations allowed anywhere)
__device__ float    g_probs[BB * LL * LRR];   // [b][j][i] — probs[b,0,i,j] in ref notation
__device__ int      g_hard[BB * LL];          // argmax per (b,j)
__device__ float    g_partial[BB];            // per-batch weighted prob sum
__device__ unsigned g_done[BB];               // per-batch block-completion counters
__device__ unsigned g_fin = 0;                // finalizer counter (self-resetting)

// Labels-dtype detect: int64 LE => every odd 32-bit word is a zero high half.
__device__ __forceinline__ void detect_is64(const int* __restrict__ lab_raw,
                                            int t, int* s_is64) {
    if (t < 32) {
        int ok  = (lab_raw[2 * t + 1] == 0);
        int all = __all_sync(0xffffffffu, ok);
        if (t == 0) *s_is64 = all;
    }
}

// Single fused kernel, one block per (b,j).
//   Phase 1: stream 32000 logits -> (sumexp, argmax); gather 128 label probs.
//   Phase 2 (last block of batch b): sudoku + weighted sum for the batch.
//   Phase 3 (last finalizer): loss = 1 - total/2048; reset counters for replay.
// __launch_bounds__(256, 8): cap regs at 32 so the cold finalize phase cannot
// cost streaming occupancy (spills, if any, land on the once-per-batch path).
__global__ __launch_bounds__(256, 8) void kfused(const float* __restrict__ logits,
                                                 const int* __restrict__ lab_raw,
                                                 float* __restrict__ out) {
    const int row  = blockIdx.x;          // b*LL + j
    const int b    = row >> 7;
    const int t    = threadIdx.x;
    const int w    = t >> 5, lane = t & 31;
    const float* __restrict__ base = logits + (size_t)row * VV;

    __shared__ float s_s[8];
    __shared__ float s_v[8];
    __shared__ int   s_i[8];
    __shared__ int   s_lab[LRR];
    __shared__ float s_inv;
    __shared__ int   s_is64;
    __shared__ unsigned s_ticket;
    // finalize-phase arrays
    __shared__ int           s_hard[LL];
    __shared__ int           s_fj[LRR];
    __shared__ int           s_colwin[LL];
    __shared__ unsigned char s_sel[LRR];
    __shared__ float         s_red[8];

    // ---- Phase 1: streaming reduce (straight-line, constant trip count) ----
    float acc0 = 0.0f, acc1 = 0.0f;
    float vmax  = -3.0e38f;
    int   kbest = t;
    const float4* b4 = (const float4*)base;
    #pragma unroll 4
    for (int it = 0; it < 31; it++) {          // 31*256 = 7936 quads, uniform
        int k = t + (it << 8);
        float4 v = __ldg(&b4[k]);
        acc0 += __expf(v.x) + __expf(v.y);     // MUFU.EX2 path
        acc1 += __expf(v.z) + __expf(v.w);
        float m = fmaxf(fmaxf(v.x, v.y), fmaxf(v.z, v.w));
        bool upd = m > vmax;                   // strict > keeps earliest quad
        kbest = upd ? k : kbest;
        vmax  = upd ? m : vmax;
    }
    if (t < 64) {                              // tail quads 7936..7999
        int k = 7936 + t;
        float4 v = __ldg(&b4[k]);
        acc0 += __expf(v.x) + __expf(v.y);
        acc1 += __expf(v.z) + __expf(v.w);
        float m = fmaxf(fmaxf(v.x, v.y), fmaxf(v.z, v.w));
        bool upd = m > vmax;
        kbest = upd ? k : kbest;
        vmax  = upd ? m : vmax;
    }
    float acc = acc0 + acc1;

    // Labels + dtype detect — only needed from here on (off the hot loop)
    detect_is64(lab_raw, t, &s_is64);
    __syncthreads();
    if (t < LRR) {
        s_lab[t] = s_is64 ? lab_raw[(b * LRR + t) * 2] : lab_raw[b * LRR + t];
    }

    // Exact element index within winning quad (L1-hit reload)
    int imax;
    {
        float4 v = __ldg(&b4[kbest]);
        int i0 = kbest << 2;
        imax = (v.x == vmax) ? i0 : (v.y == vmax) ? i0 + 1
             : (v.z == vmax) ? i0 + 2 : i0 + 3;
    }

    // warp reduce: sum + (max, first-index)
    #pragma unroll
    for (int off = 16; off; off >>= 1) {
        acc += __shfl_down_sync(0xffffffffu, acc, off);
        float ov = __shfl_down_sync(0xffffffffu, vmax, off);
        int   oi = __shfl_down_sync(0xffffffffu, imax, off);
        if (ov > vmax || (ov == vmax && oi < imax)) { vmax = ov; imax = oi; }
    }
    if (lane == 0) { s_s[w] = acc; s_v[w] = vmax; s_i[w] = imax; }
    __syncthreads();
    if (t == 0) {
        float ts = s_s[0], tv = s_v[0];
        int   ti = s_i[0];
        #pragma unroll
        for (int q = 1; q < 8; q++) {
            ts += s_s[q];
            if (s_v[q] > tv || (s_v[q] == tv && s_i[q] < ti)) { tv = s_v[q]; ti = s_i[q]; }
        }
        s_inv = 1.0f / ts;
        g_hard[row] = ti;
    }
    __syncthreads();
    if (t < LRR) {
        g_probs[row * LRR + t] = __expf(__ldg(&base[s_lab[t]])) * s_inv;
    }

    // ---- Release this block's g_hard/g_probs writes, then take a ticket ----
    __threadfence();
    if (t == 0) s_ticket = atomicAdd(&g_done[b], 1u);
    __syncthreads();
    if (s_ticket != LL - 1) return;            // not the last block of batch b

    // ---- Phase 2 (last block of batch b): sudoku + weighted sum ----
    __threadfence();                           // acquire: see all 128 blocks' writes
    if (t < LL) {
        s_hard[t]   = g_hard[b * LL + t];
        s_fj[t]     = NONE;
        s_colwin[t] = NONE;
    }
    __syncthreads();

    // Row-first: 16384 cells / 256 threads. i fast (stride-1 LDS), j broadcast.
    #pragma unroll
    for (int c = 0; c < LL * LRR; c += 256) {
        int cell = c + t;
        int i = cell & 127, j = cell >> 7;
        if (s_hard[j] == s_lab[i]) atomicMin(&s_fj[i], j);
    }
    __syncthreads();
    if (t < LRR) {
        int fj = s_fj[t];
        if (fj != NONE) atomicMin(&s_colwin[fj], t);   // column winner = min i
    }
    __syncthreads();
    if (t < LRR) {
        int fj = s_fj[t];
        s_sel[t] = (unsigned char)(fj != NONE && s_colwin[fj] == t);
    }
    __syncthreads();

    // Weighted sum: 1.0 selected; 0.5 both-unmatched; 0.1 otherwise (clip floor)
    const float* __restrict__ pb = g_probs + b * LL * LRR;
    float wacc = 0.0f;
    #pragma unroll 8
    for (int c = 0; c < LL * LRR; c += 256) {
        int cell = c + t;
        int i = cell & 127, j = cell >> 7;
        float p = pb[cell];                    // coalesced, L2-resident
        float wgt = 0.1f;
        if (s_sel[i] && s_fj[i] == j)              wgt = 1.0f;
        else if (!s_sel[i] && s_colwin[j] == NONE) wgt = 0.5f;
        wacc += wgt * p;
    }
    #pragma unroll
    for (int off = 16; off; off >>= 1)
        wacc += __shfl_down_sync(0xffffffffu, wacc, off);
    if (lane == 0) s_red[w] = wacc;
    __syncthreads();

    // ---- Phase 3: last finalizer computes the loss ----
    if (t == 0) {
        float s = 0.0f;
        #pragma unroll
        for (int q = 0; q < 8; q++) s += s_red[q];
        g_partial[b] = s;
        __threadfence();
        unsigned fin = atomicAdd(&g_fin, 1u);
        if (fin == BB - 1) {
            __threadfence();                   // acquire all g_partial
            float tot = 0.0f;
            #pragma unroll
            for (int q = 0; q < BB; q++) tot += g_partial[q];
            out[0] = 1.0f - tot * (1.0f / 2048.0f);
            // reset counters for next graph replay (all finalizers are done)
            g_fin = 0;
            #pragma unroll
            for (int q = 0; q < BB; q++) g_done[q] = 0;
        }
    }
}

extern "C" void kernel_launch(void* const* d_in, const int* in_sizes, int n_in,
                              void* d_out, int out_size) {
    // Resolve input order by element count (logits: 65.5M; labels: 2048/4096 words)
    int li = (in_sizes[0] > in_sizes[1]) ? 0 : 1;
    const float* logits = (const float*)d_in[li];
    const int*   labels = (const int*)d_in[1 - li];

    kfused<<<BB * LL, 256>>>(logits, labels, (float*)d_out);
}

// round 7
// speedup vs baseline: 1.2764x; 1.2764x over previous
#include <cuda_runtime.h>

#define BB  16
#define LL  128
#define LRR 128
#define VV  32000
#define NONE 0x7fffffff

// Scratch (no allocations allowed anywhere)
__device__ float    g_probs[BB * LL * LRR];   // [b][j][i] — probs[b,0,i,j] in ref notation
__device__ int      g_hard[BB * LL];          // argmax per (b,j)
__device__ float    g_part2[128];             // per-slice weighted prob sums
__device__ unsigned g_fin = 0;                // last-block counter (self-resetting)

// Labels-dtype detect: int64 LE => every odd 32-bit word is a zero high half.
__device__ __forceinline__ void detect_is64(const int* __restrict__ lab_raw,
                                            int t, int* s_is64) {
    if (t < 32) {
        int ok  = (lab_raw[2 * t + 1] == 0);
        int all = __all_sync(0xffffffffu, ok);
        if (t == 0) *s_is64 = all;
    }
}

// ===== k1: EXACT round-4 version (proven ~5.7 TB/s) — do not touch =====
// One block per (b,j): streaming reduce of 32000 logits -> (sumexp, argmax),
// then gather 128 label probs. exp via MUFU (__expf) keeps the FMA pipe light;
// hot loop is straight-line (predicated only) so ptxas front-batches the loads.
__global__ __launch_bounds__(256) void k1(const float* __restrict__ logits,
                                          const int* __restrict__ lab_raw) {
    const int row  = blockIdx.x;          // b*LL + j
    const int b    = row >> 7;
    const int t    = threadIdx.x;
    const int w    = t >> 5, lane = t & 31;
    const float* __restrict__ base = logits + (size_t)row * VV;

    __shared__ float s_s[8];
    __shared__ float s_v[8];
    __shared__ int   s_i[8];
    __shared__ int   s_lab[LRR];
    __shared__ float s_inv;
    __shared__ int   s_is64;

    detect_is64(lab_raw, t, &s_is64);
    __syncthreads();
    if (t < LRR) {
        s_lab[t] = s_is64 ? lab_raw[(b * LRR + t) * 2] : lab_raw[b * LRR + t];
    }

    float acc0 = 0.0f, acc1 = 0.0f;
    float vmax  = -3.0e38f;
    int   kbest = t;                       // winning quad index (exact elem found later)
    const float4* b4 = (const float4*)base;
    #pragma unroll 4
    for (int k = t; k < VV / 4; k += 256) {
        float4 v = __ldg(&b4[k]);
        acc0 += __expf(v.x) + __expf(v.y);   // MUFU.EX2 path
        acc1 += __expf(v.z) + __expf(v.w);
        float m = fmaxf(fmaxf(v.x, v.y), fmaxf(v.z, v.w));
        bool upd = m > vmax;               // strict > keeps earliest quad (first occurrence)
        kbest = upd ? k : kbest;
        vmax  = upd ? m : vmax;
    }
    float acc = acc0 + acc1;

    // Reconstruct exact element index once (quad reload hits L1)
    int imax;
    {
        float4 v = __ldg(&b4[kbest]);
        int i0 = kbest << 2;
        imax = (v.x == vmax) ? i0 : (v.y == vmax) ? i0 + 1
             : (v.z == vmax) ? i0 + 2 : i0 + 3;
    }

    // warp reduce: sum + (max, first-index) — tie -> smaller global index
    #pragma unroll
    for (int off = 16; off; off >>= 1) {
        acc += __shfl_down_sync(0xffffffffu, acc, off);
        float ov = __shfl_down_sync(0xffffffffu, vmax, off);
        int   oi = __shfl_down_sync(0xffffffffu, imax, off);
        if (ov > vmax || (ov == vmax && oi < imax)) { vmax = ov; imax = oi; }
    }
    if (lane == 0) { s_s[w] = acc; s_v[w] = vmax; s_i[w] = imax; }
    __syncthreads();
    if (t == 0) {
        float ts = s_s[0], tv = s_v[0];
        int   ti = s_i[0];
        #pragma unroll
        for (int q = 1; q < 8; q++) {
            ts += s_s[q];
            if (s_v[q] > tv || (s_v[q] == tv && s_i[q] < ti)) { tv = s_v[q]; ti = s_i[q]; }
        }
        s_inv = 1.0f / ts;
        g_hard[row] = ti;
    }
    __syncthreads();
    if (t < LRR) {
        // probs[b,0,i=t,j] = exp(logit[label]) / sumexp ; coalesced store [b][j][i]
        g_probs[row * LRR + t] = __expf(__ldg(&base[s_lab[t]])) * s_inv;
    }
}

// ===== k2: 128 blocks (8 slices per batch) =====
// Every block redundantly computes its batch's sudoku from g_hard (cheap:
// atomicMin on shared, labels ~uniform so matches are rare), then sums its
// 2048-cell slice of g_probs. Last block (ticket) does the fixed-order final
// sum over 128 partials -> deterministic; counter self-resets for graph replay.
// Weights: 1.0 selected cell; 0.5 row-and-column both unmatched; 0.1 otherwise.
__global__ __launch_bounds__(1024) void k2(const int* __restrict__ lab_raw,
                                           float* __restrict__ out) {
    const int blk   = blockIdx.x;          // 128 = 16 batches * 8 slices
    const int b     = blk >> 3;
    const int slice = blk & 7;
    const int t     = threadIdx.x;

    __shared__ int           s_hard[LL];
    __shared__ int           s_lab[LRR];
    __shared__ int           s_fj[LRR];
    __shared__ int           s_colwin[LL];
    __shared__ unsigned char s_sel[LRR];
    __shared__ float         s_red[32];
    __shared__ int           s_is64;

    detect_is64(lab_raw, t, &s_is64);
    if (t < LL) {
        s_hard[t]   = g_hard[b * LL + t];
        s_fj[t]     = NONE;
        s_colwin[t] = NONE;
    }
    __syncthreads();
    if (t < LRR) {
        s_lab[t] = s_is64 ? lab_raw[(b * LRR + t) * 2] : lab_raw[b * LRR + t];
    }
    __syncthreads();

    // Row-first: scan 16384 (i,j) cells, 16 per thread. i fast (stride-1 LDS),
    // s_hard[j] broadcast. atomicMin keeps the smallest j per row.
    #pragma unroll
    for (int c = 0; c < LL * LRR; c += 1024) {
        int cell = c + t;
        int i = cell & 127, j = cell >> 7;
        if (s_hard[j] == s_lab[i]) atomicMin(&s_fj[i], j);
    }
    __syncthreads();
    // Column dedup: winner of column fj[i] is the smallest i
    if (t < LRR) {
        int fj = s_fj[t];
        if (fj != NONE) atomicMin(&s_colwin[fj], t);
    }
    __syncthreads();
    if (t < LRR) {
        int fj = s_fj[t];
        s_sel[t] = (unsigned char)(fj != NONE && s_colwin[fj] == t);
    }
    __syncthreads();

    // This block's slice: cells [slice*2048, slice*2048+2048), 2 per thread
    const float* __restrict__ pb = g_probs + b * LL * LRR;
    float acc = 0.0f;
    #pragma unroll
    for (int kq = 0; kq < 2; kq++) {
        int cell = slice * 2048 + kq * 1024 + t;
        int i = cell & 127, j = cell >> 7;
        float p = pb[cell];                          // coalesced, L2-resident
        float wgt = 0.1f;
        if (s_sel[i] && s_fj[i] == j)              wgt = 1.0f;  // selected match
        else if (!s_sel[i] && s_colwin[j] == NONE) wgt = 0.5f;  // both unmatched
        acc += wgt * p;
    }

    // Block reduce (deterministic order)
    #pragma unroll
    for (int off = 16; off; off >>= 1)
        acc += __shfl_down_sync(0xffffffffu, acc, off);
    if ((t & 31) == 0) s_red[t >> 5] = acc;
    __syncthreads();
    if (t == 0) {
        float s = 0.0f;
        #pragma unroll
        for (int q = 0; q < 32; q++) s += s_red[q];
        g_part2[blk] = s;
        __threadfence();                   // release partial before ticket
        unsigned ticket = atomicAdd(&g_fin, 1u);
        if (ticket == 127) {
            __threadfence();               // acquire all partials
            float tot = 0.0f;
            #pragma unroll
            for (int q = 0; q < 128; q++) tot += g_part2[q];
            // loss = 1 + mean_b(-2*total_b/256) = 1 - tot/2048
            out[0] = 1.0f - tot * (1.0f / 2048.0f);
            g_fin = 0;                     // reset for next graph replay
        }
    }
}

extern "C" void kernel_launch(void* const* d_in, const int* in_sizes, int n_in,
                              void* d_out, int out_size) {
    // Resolve input order by element count (logits: 65.5M; labels: 2048/4096 words)
    int li = (in_sizes[0] > in_sizes[1]) ? 0 : 1;
    const float* logits = (const float*)d_in[li];
    const int*   labels = (const int*)d_in[1 - li];

    k1<<<BB * LL, 256>>>(logits, labels);
    k2<<<128, 1024>>>(labels, (float*)d_out);
}